// round 16
// baseline (speedup 1.0000x reference)
#include <cuda_runtime.h>
#include <cuda_bf16.h>
#include <cstdint>

#define NNODES 50000
#define NEDGES 640000
#define MDIM 128
#define DDIM 128
#define HDIM 64

// ---------------- device scratch (static, no runtime alloc) ----------------
__device__ __nv_bfloat16 g_P[(size_t)NNODES * HDIM]; // per-node projected feats + b1 (bf16)
__device__ float g_sumw[NNODES];                 // sum of weights per node
__device__ __nv_bfloat16 g_W1m[HDIM * MDIM];     // W1[:, :128]  (message half), bf16
__device__ __nv_bfloat16 g_W1t[HDIM * DDIM];     // W1[:, 128:]  (node half),    bf16

#define LDA 136              // bf16 elements per row (8-elem pad -> conflict-free ldmatrix)
#define LDAB (LDA * 2)       // 272 bytes

// ------- pnode smem layout (C roundtrips through smem) -------
#define SM_VEC 0
#define SM_A 1280
#define SM_B (1280 + 34816)
#define SMEM_BYTES (SM_B + 17408)

// ------- edge smem layout (M=128 tile, 256 threads) -------
#define E_VEC 0              // 64 floats: W2 (256 B)
#define E_TG 256             // 128 ints: targets (512 B)
#define E_A 1024             // A bf16 [128][136] = 34816 B
#define E_B (1024 + 34816)   // B bf16 [64][136]  = 17408 B
#define E_SMEM (E_B + 17408) // 53248 B -> 2 CTAs/SM (reg-capped anyway)
#define EM 128               // edges per CTA

// ---------------- helpers ----------------
__device__ __forceinline__ uint32_t smem_u32(const void* p) {
    uint32_t a;
    asm("{ .reg .u64 t; cvta.to.shared.u64 t, %1; cvt.u32.u64 %0, t; }" : "=r"(a) : "l"(p));
    return a;
}

__device__ __forceinline__ void ldm4(uint32_t& r0, uint32_t& r1, uint32_t& r2, uint32_t& r3,
                                     uint32_t addr) {
    asm volatile("ldmatrix.sync.aligned.m8n8.x4.shared.b16 {%0,%1,%2,%3}, [%4];"
                 : "=r"(r0), "=r"(r1), "=r"(r2), "=r"(r3) : "r"(addr));
}

__device__ __forceinline__ void mma16816(float* c, uint32_t a0, uint32_t a1, uint32_t a2,
                                         uint32_t a3, uint32_t b0, uint32_t b1) {
    asm volatile(
        "mma.sync.aligned.m16n8k16.row.col.f32.bf16.bf16.f32 "
        "{%0,%1,%2,%3}, {%4,%5,%6,%7}, {%8,%9}, {%0,%1,%2,%3};"
        : "+f"(c[0]), "+f"(c[1]), "+f"(c[2]), "+f"(c[3])
        : "r"(a0), "r"(a1), "r"(a2), "r"(a3), "r"(b0), "r"(b1));
}

__device__ __forceinline__ void red_add_v4(float* addr, float4 v) {
    asm volatile("red.global.add.v4.f32 [%0], {%1,%2,%3,%4};"
                 :: "l"(addr), "f"(v.x), "f"(v.y), "f"(v.z), "f"(v.w) : "memory");
}

// tanh-form gelu via MUFU ex2+rcp (R9-proven)
__device__ __forceinline__ float gelu_fast(float x) {
    float t = 1.5957692f * fmaf(0.044715f * x, x * x, x);
    return __fdividef(x, 1.0f + __expf(-t));
}

// ---------------- 128x64 GEMM (pnode only): C -> smem at SM_A ----------------
__device__ __forceinline__ void gemm_128x64(char* smem, uint32_t sb, int wid, int lid) {
    float c[2][8][4];
#pragma unroll
    for (int t = 0; t < 2; t++)
#pragma unroll
        for (int n = 0; n < 8; n++)
#pragma unroll
            for (int j = 0; j < 4; j++) c[t][n][j] = 0.f;

    const int lrow = lid & 15;
    const int lcol = (lid >> 4) * 8;

#pragma unroll
    for (int k = 0; k < 8; k++) {
        const uint32_t kc = (uint32_t)(k * 16 + lcol) * 2;
        uint32_t af[2][4], bf[4][4];
        uint32_t A0 = sb + SM_A + (uint32_t)(wid * 32 + lrow) * LDAB + kc;
        ldm4(af[0][0], af[0][1], af[0][2], af[0][3], A0);
        ldm4(af[1][0], af[1][1], af[1][2], af[1][3], A0 + 16 * LDAB);
#pragma unroll
        for (int g = 0; g < 4; g++) {
            uint32_t B0 = sb + SM_B + (uint32_t)(g * 16 + lrow) * LDAB + kc;
            ldm4(bf[g][0], bf[g][1], bf[g][2], bf[g][3], B0);
        }
#pragma unroll
        for (int t = 0; t < 2; t++)
#pragma unroll
            for (int n = 0; n < 8; n++)
                mma16816(c[t][n], af[t][0], af[t][1], af[t][2], af[t][3],
                         bf[n >> 1][n & 1], bf[n >> 1][(n & 1) + 2]);
    }
    __syncthreads();
#pragma unroll
    for (int t = 0; t < 2; t++) {
        int r0 = wid * 32 + t * 16 + (lid >> 2);
#pragma unroll
        for (int n = 0; n < 8; n++) {
            int col = n * 8 + (lid & 3) * 2;
            *(float2*)(smem + SM_A + r0 * LDAB + col * 4) = make_float2(c[t][n][0], c[t][n][1]);
            *(float2*)(smem + SM_A + (r0 + 8) * LDAB + col * 4) = make_float2(c[t][n][2], c[t][n][3]);
        }
    }
    __syncthreads();
}

// ---------------- prep: W1 fp32 -> bf16 halves (tiny, must precede pnode) ----------
__global__ void prep_kernel(const float* __restrict__ W1) {
    int i = blockIdx.x * blockDim.x + threadIdx.x;
    if (i < HDIM * MDIM) {
        int row = i >> 7, k = i & 127;
        g_W1m[i] = __float2bfloat16(W1[row * 256 + k]);
        g_W1t[i] = __float2bfloat16(W1[row * 256 + 128 + k]);
    }
}

// ---------------- pnode: zero agg/sumw (grid-stride) + P = nf @ W1t^T + b1 ---------
__global__ void __launch_bounds__(128) pnode_kernel(const float* __restrict__ nf,
                                                    const float* __restrict__ b1,
                                                    float* __restrict__ agg) {
    extern __shared__ char smem[];
    const uint32_t sb = smem_u32(smem);
    const int tid = threadIdx.x, wid = tid >> 5, lid = tid & 31;
    const int base = blockIdx.x * 128;

    // zero agg + sumw (overlaps with staging/GEMM across CTAs; edge launches later)
    {
        int gi = blockIdx.x * 128 + tid;
        int gs = gridDim.x * 128;
        float4 z = make_float4(0.f, 0.f, 0.f, 0.f);
        for (int j = gi; j < NNODES * MDIM / 4; j += gs) ((float4*)agg)[j] = z;
        for (int j = gi; j < NNODES; j += gs) g_sumw[j] = 0.f;
    }

    // B = W1t copied as uint4
    const uint4* Bsrc = (const uint4*)g_W1t;
    for (int i = tid; i < HDIM * 16; i += 128) {
        int row = i >> 4, c16 = i & 15;
        *(uint4*)(smem + SM_B + row * LDAB + c16 * 16) = Bsrc[row * 16 + c16];
    }
    const float4* nf4 = (const float4*)nf;
    for (int i = tid; i < 128 * 32; i += 128) {
        int row = i >> 5, c4 = i & 31;
        int node = base + row;
        float4 v = (node < NNODES) ? nf4[(size_t)node * 32 + c4] : make_float4(0.f, 0.f, 0.f, 0.f);
        __nv_bfloat162 lo = __floats2bfloat162_rn(v.x, v.y);
        __nv_bfloat162 hi = __floats2bfloat162_rn(v.z, v.w);
        uint2 u;
        u.x = *(uint32_t*)&lo;
        u.y = *(uint32_t*)&hi;
        *(uint2*)(smem + SM_A + row * LDAB + c4 * 8) = u;
    }
    if (tid < 64) ((float*)(smem + SM_VEC))[tid] = b1[tid];
    __syncthreads();

    gemm_128x64(smem, sb, wid, lid);

    int node = base + tid;
    if (node < NNODES) {
        const float* sb1 = (const float*)(smem + SM_VEC);
        const float* Crow = (const float*)(smem + SM_A + tid * LDAB);
        uint32_t* Pr = (uint32_t*)(g_P + (size_t)node * HDIM);
#pragma unroll
        for (int j = 0; j < 16; j++) {
            float4 cv = ((const float4*)Crow)[j];
            __nv_bfloat162 p0 = __floats2bfloat162_rn(cv.x + sb1[4 * j], cv.y + sb1[4 * j + 1]);
            __nv_bfloat162 p1 = __floats2bfloat162_rn(cv.z + sb1[4 * j + 2], cv.w + sb1[4 * j + 3]);
            Pr[2 * j] = *(uint32_t*)&p0;
            Pr[2 * j + 1] = *(uint32_t*)&p1;
        }
    }
}

// ---------------- main edge kernel: 256 threads, 8 warps x 16 rows ----------------
__global__ void __launch_bounds__(256, 2) edge_kernel(const float* __restrict__ msg,
                                                      const int* __restrict__ tgt,
                                                      const float* __restrict__ W2,
                                                      float* __restrict__ agg) {
    extern __shared__ char smem[];
    const uint32_t sb = smem_u32(smem);
    const int tid = threadIdx.x, wid = tid >> 5, lid = tid & 31;
    const int base = blockIdx.x * EM;
    const int R = wid * 16;                 // this warp's 16 rows (stage+epilogue+scatter)

    // --- 1) issue ALL message DRAM loads first (MLP=16 outstanding) ---
    const float4* m4 = (const float4*)msg + (size_t)base * 32;
    float4 mreg[16];                        // rows R+s, cols [4*lid, 4*lid+3]
#pragma unroll
    for (int s = 0; s < 16; s++) mreg[s] = m4[(R + s) * 32 + lid];

    // --- 2) B = W1m copied as uint4 (L2-hot; overlaps in-flight A loads) ---
    const uint4* Bsrc = (const uint4*)g_W1m;
#pragma unroll
    for (int i = tid; i < HDIM * 16; i += 256) {
        int row = i >> 4, c16 = i & 15;
        *(uint4*)(smem + E_B + row * LDAB + c16 * 16) = Bsrc[row * 16 + c16];
    }
    if (tid < 64) ((float*)(smem + E_VEC))[tid] = W2[tid];
    if (tid < EM) ((int*)(smem + E_TG))[tid] = tgt[base + tid];

    // --- 3) convert + store A (data has landed by now) ---
#pragma unroll
    for (int s = 0; s < 16; s++) {
        const int row = R + s;
        float4 v = mreg[s];
        __nv_bfloat162 lo = __floats2bfloat162_rn(v.x, v.y);
        __nv_bfloat162 hi = __floats2bfloat162_rn(v.z, v.w);
        uint2 u;
        u.x = *(uint32_t*)&lo;
        u.y = *(uint32_t*)&hi;
        *(uint2*)(smem + E_A + row * LDAB + lid * 8) = u;
    }
    __syncthreads();       // only CTA-wide barrier in the kernel

    // --- P prefetch (bf16x2 words; hide L2 gather latency behind GEMM) ---
    const int* st = (const int*)(smem + E_TG);
    const int qr = lid >> 2, ql = lid & 3;
    const int te0 = st[R + qr];
    const int te1 = st[R + qr + 8];
    const uint32_t* Pr0 = (const uint32_t*)(g_P + (size_t)te0 * HDIM);
    const uint32_t* Pr1 = (const uint32_t*)(g_P + (size_t)te1 * HDIM);
    uint32_t pf0[8], pf1[8];
#pragma unroll
    for (int n = 0; n < 8; n++) {
        pf0[n] = Pr0[n * 4 + ql];
        pf1[n] = Pr1[n * 4 + ql];
    }

    // --- GEMM: one m16n64k128 tile per warp, C in registers ---
    float c[8][4];
#pragma unroll
    for (int n = 0; n < 8; n++)
#pragma unroll
        for (int j = 0; j < 4; j++) c[n][j] = 0.f;

    const int lrow = lid & 15;
    const int lcolb = (lid >> 4) * 8;
#pragma unroll
    for (int k = 0; k < 8; k++) {
        const uint32_t kc = (uint32_t)(k * 16 + lcolb) * 2;
        uint32_t af[4], bf[4][4];
        ldm4(af[0], af[1], af[2], af[3], sb + E_A + (uint32_t)(R + lrow) * LDAB + kc);
#pragma unroll
        for (int g = 0; g < 4; g++)
            ldm4(bf[g][0], bf[g][1], bf[g][2], bf[g][3],
                 sb + E_B + (uint32_t)(g * 16 + lrow) * LDAB + kc);
#pragma unroll
        for (int n = 0; n < 8; n++)
            mma16816(c[n], af[0], af[1], af[2], af[3],
                     bf[n >> 1][n & 1], bf[n >> 1][(n & 1) + 2]);
    }

    // --- epilogue: scores for this warp's 16 rows via quad reduction ---
    const float2* sW2 = (const float2*)(smem + E_VEC);
    float r0 = 0.f, r1 = 0.f;
#pragma unroll
    for (int n = 0; n < 8; n++) {
        float2 w2 = sW2[n * 4 + ql];
        float2 p0 = __bfloat1622float2(*(const __nv_bfloat162*)&pf0[n]);
        float2 p1 = __bfloat1622float2(*(const __nv_bfloat162*)&pf1[n]);
        r0 = fmaf(gelu_fast(c[n][0] + p0.x), w2.x, r0);
        r0 = fmaf(gelu_fast(c[n][1] + p0.y), w2.y, r0);
        r1 = fmaf(gelu_fast(c[n][2] + p1.x), w2.x, r1);
        r1 = fmaf(gelu_fast(c[n][3] + p1.y), w2.y, r1);
    }
    r0 += __shfl_xor_sync(0xffffffffu, r0, 1);
    r0 += __shfl_xor_sync(0xffffffffu, r0, 2);
    r1 += __shfl_xor_sync(0xffffffffu, r1, 1);
    r1 += __shfl_xor_sync(0xffffffffu, r1, 2);
    float w0 = __fdividef(1.f, 1.f + __expf(-r0));
    float w1 = __fdividef(1.f, 1.f + __expf(-r1));
    if (ql == 0) {
        atomicAdd(&g_sumw[te0], w0);
        atomicAdd(&g_sumw[te1], w1);
    }

    // --- scatter: same 16 rows, weights/targets broadcast in-warp (no barrier) ---
#pragma unroll
    for (int s = 0; s < 16; s++) {
        const int src = (s & 7) << 2;       // quad-leader lane for row R+s
        float w = __shfl_sync(0xffffffffu, s < 8 ? w0 : w1, src);
        int te = __shfl_sync(0xffffffffu, s < 8 ? te0 : te1, src);
        float4 v = mreg[s];
        red_add_v4(agg + (size_t)te * 128 + lid * 4,
                   make_float4(v.x * w, v.y * w, v.z * w, v.w * w));
    }
}

// ---------------- finalize: 2 nodes per warp (interleaved chains) ----------------
__global__ void finalize_kernel(float* __restrict__ agg,
                                const float* __restrict__ gamma,
                                const float* __restrict__ beta) {
    int wid = threadIdx.x >> 5, lid = threadIdx.x & 31;
    int n0 = blockIdx.x * 16 + wid * 2;     // 50000 % 16 == 0: both nodes always valid
    float sw0 = g_sumw[n0];
    float sw1 = g_sumw[n0 + 1];
    float4 v0 = ((const float4*)(agg + (size_t)n0 * 128))[lid];
    float4 v1 = ((const float4*)(agg + (size_t)(n0 + 1) * 128))[lid];
    float4 g = ((const float4*)gamma)[lid];
    float4 b = ((const float4*)beta)[lid];
    float inv0 = __fdividef(1.f, sw0 + 1e-8f);
    float inv1 = __fdividef(1.f, sw1 + 1e-8f);
    v0.x *= inv0; v0.y *= inv0; v0.z *= inv0; v0.w *= inv0;
    v1.x *= inv1; v1.y *= inv1; v1.z *= inv1; v1.w *= inv1;
    float s0 = v0.x + v0.y + v0.z + v0.w;
    float q0 = fmaf(v0.x, v0.x, fmaf(v0.y, v0.y, fmaf(v0.z, v0.z, v0.w * v0.w)));
    float s1 = v1.x + v1.y + v1.z + v1.w;
    float q1 = fmaf(v1.x, v1.x, fmaf(v1.y, v1.y, fmaf(v1.z, v1.z, v1.w * v1.w)));
#pragma unroll
    for (int o = 16; o; o >>= 1) {
        s0 += __shfl_xor_sync(0xffffffff, s0, o);
        q0 += __shfl_xor_sync(0xffffffff, q0, o);
        s1 += __shfl_xor_sync(0xffffffff, s1, o);
        q1 += __shfl_xor_sync(0xffffffff, q1, o);
    }
    float mu0 = s0 * (1.f / 128.f);
    float mu1 = s1 * (1.f / 128.f);
    float rs0 = rsqrtf(fmaf(-mu0, mu0, q0 * (1.f / 128.f)) + 1e-5f);
    float rs1 = rsqrtf(fmaf(-mu1, mu1, q1 * (1.f / 128.f)) + 1e-5f);
    ((float4*)(agg + (size_t)n0 * 128))[lid] =
        make_float4((v0.x - mu0) * rs0 * g.x + b.x, (v0.y - mu0) * rs0 * g.y + b.y,
                    (v0.z - mu0) * rs0 * g.z + b.z, (v0.w - mu0) * rs0 * g.w + b.w);
    ((float4*)(agg + (size_t)(n0 + 1) * 128))[lid] =
        make_float4((v1.x - mu1) * rs1 * g.x + b.x, (v1.y - mu1) * rs1 * g.y + b.y,
                    (v1.z - mu1) * rs1 * g.z + b.z, (v1.w - mu1) * rs1 * g.w + b.w);
}

// ---------------- launch ----------------
extern "C" void kernel_launch(void* const* d_in, const int* in_sizes, int n_in,
                              void* d_out, int out_size) {
    const float* msg = (const float*)d_in[0];
    const int* tgt = (const int*)d_in[1];
    const float* nf = (const float*)d_in[2];
    int wi = 3;
    for (int i = 3; i < n_in; i++) {
        if (in_sizes[i] == HDIM * (MDIM + DDIM)) { wi = i; break; }
    }
    const float* W1 = (const float*)d_in[wi];
    const float* b1 = (const float*)d_in[wi + 1];
    const float* W2 = (const float*)d_in[wi + 2];
    const float* gamma = (const float*)d_in[wi + 3];
    const float* beta = (const float*)d_in[wi + 4];
    float* agg = (float*)d_out;

    cudaFuncSetAttribute(pnode_kernel, cudaFuncAttributeMaxDynamicSharedMemorySize, SMEM_BYTES);
    cudaFuncSetAttribute(edge_kernel, cudaFuncAttributeMaxDynamicSharedMemorySize, E_SMEM);

    prep_kernel<<<32, 256>>>(W1);
    pnode_kernel<<<(NNODES + 127) / 128, 128, SMEM_BYTES>>>(nf, b1, agg);
    edge_kernel<<<NEDGES / EM, 256, E_SMEM>>>(msg, tgt, W2, agg);
    finalize_kernel<<<NNODES / 16, 256>>>(agg, gamma, beta);
}

// round 17
// speedup vs baseline: 1.1022x; 1.1022x over previous
#include <cuda_runtime.h>
#include <cuda_bf16.h>
#include <cstdint>

#define NNODES 50000
#define NEDGES 640000
#define MDIM 128
#define DDIM 128
#define HDIM 64

// ---------------- device scratch (static, no runtime alloc) ----------------
__device__ __nv_bfloat16 g_P[(size_t)NNODES * HDIM]; // per-node projected feats + b1 (bf16)
__device__ float g_sumw[NNODES];                 // sum of weights per node
__device__ __nv_bfloat16 g_W1m[HDIM * MDIM];     // W1[:, :128]  (message half), bf16
__device__ __nv_bfloat16 g_W1t[HDIM * DDIM];     // W1[:, 128:]  (node half),    bf16

#define LDA 136              // bf16 elements per row (8-elem pad -> conflict-free ldmatrix)
#define LDAB (LDA * 2)       // 272 bytes

// ------- pnode smem layout (C roundtrips through smem) -------
#define SM_VEC 0
#define SM_A 1280
#define SM_B (1280 + 34816)
#define SMEM_BYTES (SM_B + 17408)

// ------- edge smem layout (M=64 tile, 128 threads — R15 champion config) -------
#define E_VEC 0              // 64 floats: W2
#define E_TG 512             // 64 ints: targets
#define E_A 1024             // A bf16 [64][136] = 17408 B
#define E_B (1024 + 17408)   // B bf16 [64][136] = 17408 B
#define E_SMEM (E_B + 17408) // 35840 B
#define EM 64                // edges per CTA

// ---------------- helpers ----------------
__device__ __forceinline__ uint32_t smem_u32(const void* p) {
    uint32_t a;
    asm("{ .reg .u64 t; cvta.to.shared.u64 t, %1; cvt.u32.u64 %0, t; }" : "=r"(a) : "l"(p));
    return a;
}

__device__ __forceinline__ void ldm4(uint32_t& r0, uint32_t& r1, uint32_t& r2, uint32_t& r3,
                                     uint32_t addr) {
    asm volatile("ldmatrix.sync.aligned.m8n8.x4.shared.b16 {%0,%1,%2,%3}, [%4];"
                 : "=r"(r0), "=r"(r1), "=r"(r2), "=r"(r3) : "r"(addr));
}

__device__ __forceinline__ void mma16816(float* c, uint32_t a0, uint32_t a1, uint32_t a2,
                                         uint32_t a3, uint32_t b0, uint32_t b1) {
    asm volatile(
        "mma.sync.aligned.m16n8k16.row.col.f32.bf16.bf16.f32 "
        "{%0,%1,%2,%3}, {%4,%5,%6,%7}, {%8,%9}, {%0,%1,%2,%3};"
        : "+f"(c[0]), "+f"(c[1]), "+f"(c[2]), "+f"(c[3])
        : "r"(a0), "r"(a1), "r"(a2), "r"(a3), "r"(b0), "r"(b1));
}

__device__ __forceinline__ void red_add_v4(float* addr, float4 v) {
    asm volatile("red.global.add.v4.f32 [%0], {%1,%2,%3,%4};"
                 :: "l"(addr), "f"(v.x), "f"(v.y), "f"(v.z), "f"(v.w) : "memory");
}

// tanh-form gelu via MUFU ex2+rcp (R9-proven)
__device__ __forceinline__ float gelu_fast(float x) {
    float t = 1.5957692f * fmaf(0.044715f * x, x * x, x);
    return __fdividef(x, 1.0f + __expf(-t));
}

// ---------------- 128x64 GEMM (pnode only): C -> smem at SM_A ----------------
__device__ __forceinline__ void gemm_128x64(char* smem, uint32_t sb, int wid, int lid) {
    float c[2][8][4];
#pragma unroll
    for (int t = 0; t < 2; t++)
#pragma unroll
        for (int n = 0; n < 8; n++)
#pragma unroll
            for (int j = 0; j < 4; j++) c[t][n][j] = 0.f;

    const int lrow = lid & 15;
    const int lcol = (lid >> 4) * 8;

#pragma unroll
    for (int k = 0; k < 8; k++) {
        const uint32_t kc = (uint32_t)(k * 16 + lcol) * 2;
        uint32_t af[2][4], bf[4][4];
        uint32_t A0 = sb + SM_A + (uint32_t)(wid * 32 + lrow) * LDAB + kc;
        ldm4(af[0][0], af[0][1], af[0][2], af[0][3], A0);
        ldm4(af[1][0], af[1][1], af[1][2], af[1][3], A0 + 16 * LDAB);
#pragma unroll
        for (int g = 0; g < 4; g++) {
            uint32_t B0 = sb + SM_B + (uint32_t)(g * 16 + lrow) * LDAB + kc;
            ldm4(bf[g][0], bf[g][1], bf[g][2], bf[g][3], B0);
        }
#pragma unroll
        for (int t = 0; t < 2; t++)
#pragma unroll
            for (int n = 0; n < 8; n++)
                mma16816(c[t][n], af[t][0], af[t][1], af[t][2], af[t][3],
                         bf[n >> 1][n & 1], bf[n >> 1][(n & 1) + 2]);
    }
    __syncthreads();
#pragma unroll
    for (int t = 0; t < 2; t++) {
        int r0 = wid * 32 + t * 16 + (lid >> 2);
#pragma unroll
        for (int n = 0; n < 8; n++) {
            int col = n * 8 + (lid & 3) * 2;
            *(float2*)(smem + SM_A + r0 * LDAB + col * 4) = make_float2(c[t][n][0], c[t][n][1]);
            *(float2*)(smem + SM_A + (r0 + 8) * LDAB + col * 4) = make_float2(c[t][n][2], c[t][n][3]);
        }
    }
    __syncthreads();
}

// ---------------- prep: W1 fp32 -> bf16 halves (tiny, must precede pnode) ----------
__global__ void prep_kernel(const float* __restrict__ W1) {
    int i = blockIdx.x * blockDim.x + threadIdx.x;
    if (i < HDIM * MDIM) {
        int row = i >> 7, k = i & 127;
        g_W1m[i] = __float2bfloat16(W1[row * 256 + k]);
        g_W1t[i] = __float2bfloat16(W1[row * 256 + 128 + k]);
    }
}

// ---------------- pnode: zero agg/sumw (grid-stride) + P = nf @ W1t^T + b1 ---------
__global__ void __launch_bounds__(128) pnode_kernel(const float* __restrict__ nf,
                                                    const float* __restrict__ b1,
                                                    float* __restrict__ agg) {
    extern __shared__ char smem[];
    const uint32_t sb = smem_u32(smem);
    const int tid = threadIdx.x, wid = tid >> 5, lid = tid & 31;
    const int base = blockIdx.x * 128;

    // zero agg + sumw (overlaps with staging/GEMM across CTAs; edge launches later)
    {
        int gi = blockIdx.x * 128 + tid;
        int gs = gridDim.x * 128;
        float4 z = make_float4(0.f, 0.f, 0.f, 0.f);
        for (int j = gi; j < NNODES * MDIM / 4; j += gs) ((float4*)agg)[j] = z;
        for (int j = gi; j < NNODES; j += gs) g_sumw[j] = 0.f;
    }

    // B = W1t copied as uint4
    const uint4* Bsrc = (const uint4*)g_W1t;
    for (int i = tid; i < HDIM * 16; i += 128) {
        int row = i >> 4, c16 = i & 15;
        *(uint4*)(smem + SM_B + row * LDAB + c16 * 16) = Bsrc[row * 16 + c16];
    }
    const float4* nf4 = (const float4*)nf;
    for (int i = tid; i < 128 * 32; i += 128) {
        int row = i >> 5, c4 = i & 31;
        int node = base + row;
        float4 v = (node < NNODES) ? nf4[(size_t)node * 32 + c4] : make_float4(0.f, 0.f, 0.f, 0.f);
        __nv_bfloat162 lo = __floats2bfloat162_rn(v.x, v.y);
        __nv_bfloat162 hi = __floats2bfloat162_rn(v.z, v.w);
        uint2 u;
        u.x = *(uint32_t*)&lo;
        u.y = *(uint32_t*)&hi;
        *(uint2*)(smem + SM_A + row * LDAB + c4 * 8) = u;
    }
    if (tid < 64) ((float*)(smem + SM_VEC))[tid] = b1[tid];
    __syncthreads();

    gemm_128x64(smem, sb, wid, lid);

    int node = base + tid;
    if (node < NNODES) {
        const float* sb1 = (const float*)(smem + SM_VEC);
        const float* Crow = (const float*)(smem + SM_A + tid * LDAB);
        uint32_t* Pr = (uint32_t*)(g_P + (size_t)node * HDIM);
#pragma unroll
        for (int j = 0; j < 16; j++) {
            float4 cv = ((const float4*)Crow)[j];
            __nv_bfloat162 p0 = __floats2bfloat162_rn(cv.x + sb1[4 * j], cv.y + sb1[4 * j + 1]);
            __nv_bfloat162 p1 = __floats2bfloat162_rn(cv.z + sb1[4 * j + 2], cv.w + sb1[4 * j + 3]);
            Pr[2 * j] = *(uint32_t*)&p0;
            Pr[2 * j + 1] = *(uint32_t*)&p1;
        }
    }
}

// ---------------- main edge kernel: R15 champion (EM=64, 128 thr, 4 CTAs/SM) -------
__global__ void __launch_bounds__(128, 4) edge_kernel(const float* __restrict__ msg,
                                                      const int* __restrict__ tgt,
                                                      const float* __restrict__ W2,
                                                      float* __restrict__ agg) {
    extern __shared__ char smem[];
    const uint32_t sb = smem_u32(smem);
    const int tid = threadIdx.x, wid = tid >> 5, lid = tid & 31;
    const int base = blockIdx.x * EM;
    const int R = wid * 16;                 // this warp's 16 rows (stage+epilogue+scatter)

    // --- 1) issue ALL message DRAM loads first (MLP=16 outstanding) ---
    const float4* m4 = (const float4*)msg + (size_t)base * 32;
    float4 mreg[16];                        // rows R+s, cols [4*lid, 4*lid+3]
#pragma unroll
    for (int s = 0; s < 16; s++) mreg[s] = m4[(R + s) * 32 + lid];

    // --- 2) B = W1m copied as uint4 (L1/L2-hot; overlaps in-flight A loads) ---
    const uint4* Bsrc = (const uint4*)g_W1m;
#pragma unroll
    for (int i = tid; i < HDIM * 16; i += 128) {
        int row = i >> 4, c16 = i & 15;
        *(uint4*)(smem + E_B + row * LDAB + c16 * 16) = Bsrc[row * 16 + c16];
    }
    if (tid < 64) ((float*)(smem + E_VEC))[tid] = W2[tid];
    if (tid < EM) ((int*)(smem + E_TG))[tid] = tgt[base + tid];

    // --- 3) convert + store A (data has landed by now) ---
#pragma unroll
    for (int s = 0; s < 16; s++) {
        const int row = R + s;
        float4 v = mreg[s];
        __nv_bfloat162 lo = __floats2bfloat162_rn(v.x, v.y);
        __nv_bfloat162 hi = __floats2bfloat162_rn(v.z, v.w);
        uint2 u;
        u.x = *(uint32_t*)&lo;
        u.y = *(uint32_t*)&hi;
        *(uint2*)(smem + E_A + row * LDAB + lid * 8) = u;
    }
    __syncthreads();       // only CTA-wide barrier in the kernel

    // --- P prefetch (bf16x2 words; hide L2 gather latency behind GEMM) ---
    const int* st = (const int*)(smem + E_TG);
    const int qr = lid >> 2, ql = lid & 3;
    const int te0 = st[R + qr];
    const int te1 = st[R + qr + 8];
    const uint32_t* Pr0 = (const uint32_t*)(g_P + (size_t)te0 * HDIM);
    const uint32_t* Pr1 = (const uint32_t*)(g_P + (size_t)te1 * HDIM);
    uint32_t pf0[8], pf1[8];
#pragma unroll
    for (int n = 0; n < 8; n++) {
        pf0[n] = Pr0[n * 4 + ql];
        pf1[n] = Pr1[n * 4 + ql];
    }

    // --- GEMM: one m16n64k128 tile per warp, C in registers ---
    float c[8][4];
#pragma unroll
    for (int n = 0; n < 8; n++)
#pragma unroll
        for (int j = 0; j < 4; j++) c[n][j] = 0.f;

    const int lrow = lid & 15;
    const int lcolb = (lid >> 4) * 8;
#pragma unroll
    for (int k = 0; k < 8; k++) {
        const uint32_t kc = (uint32_t)(k * 16 + lcolb) * 2;
        uint32_t af[4], bf[4][4];
        ldm4(af[0], af[1], af[2], af[3], sb + E_A + (uint32_t)(R + lrow) * LDAB + kc);
#pragma unroll
        for (int g = 0; g < 4; g++)
            ldm4(bf[g][0], bf[g][1], bf[g][2], bf[g][3],
                 sb + E_B + (uint32_t)(g * 16 + lrow) * LDAB + kc);
#pragma unroll
        for (int n = 0; n < 8; n++)
            mma16816(c[n], af[0], af[1], af[2], af[3],
                     bf[n >> 1][n & 1], bf[n >> 1][(n & 1) + 2]);
    }

    // --- epilogue: scores for this warp's 16 rows via quad reduction ---
    const float2* sW2 = (const float2*)(smem + E_VEC);
    float r0 = 0.f, r1 = 0.f;
#pragma unroll
    for (int n = 0; n < 8; n++) {
        float2 w2 = sW2[n * 4 + ql];
        float2 p0 = __bfloat1622float2(*(const __nv_bfloat162*)&pf0[n]);
        float2 p1 = __bfloat1622float2(*(const __nv_bfloat162*)&pf1[n]);
        r0 = fmaf(gelu_fast(c[n][0] + p0.x), w2.x, r0);
        r0 = fmaf(gelu_fast(c[n][1] + p0.y), w2.y, r0);
        r1 = fmaf(gelu_fast(c[n][2] + p1.x), w2.x, r1);
        r1 = fmaf(gelu_fast(c[n][3] + p1.y), w2.y, r1);
    }
    r0 += __shfl_xor_sync(0xffffffffu, r0, 1);
    r0 += __shfl_xor_sync(0xffffffffu, r0, 2);
    r1 += __shfl_xor_sync(0xffffffffu, r1, 1);
    r1 += __shfl_xor_sync(0xffffffffu, r1, 2);
    float w0 = __fdividef(1.f, 1.f + __expf(-r0));
    float w1 = __fdividef(1.f, 1.f + __expf(-r1));
    if (ql == 0) {
        atomicAdd(&g_sumw[te0], w0);
        atomicAdd(&g_sumw[te1], w1);
    }

    // --- scatter: same 16 rows, weights/targets broadcast in-warp (no barrier) ---
#pragma unroll
    for (int s = 0; s < 16; s++) {
        const int src = (s & 7) << 2;       // quad-leader lane for row R+s
        float w = __shfl_sync(0xffffffffu, s < 8 ? w0 : w1, src);
        int te = __shfl_sync(0xffffffffu, s < 8 ? te0 : te1, src);
        float4 v = mreg[s];
        red_add_v4(agg + (size_t)te * 128 + lid * 4,
                   make_float4(v.x * w, v.y * w, v.z * w, v.w * w));
    }
}

// ---------------- finalize: 2 nodes per warp (interleaved chains) ----------------
__global__ void finalize_kernel(float* __restrict__ agg,
                                const float* __restrict__ gamma,
                                const float* __restrict__ beta) {
    int wid = threadIdx.x >> 5, lid = threadIdx.x & 31;
    int n0 = blockIdx.x * 16 + wid * 2;     // 50000 % 16 == 0: both nodes always valid
    float sw0 = g_sumw[n0];
    float sw1 = g_sumw[n0 + 1];
    float4 v0 = ((const float4*)(agg + (size_t)n0 * 128))[lid];
    float4 v1 = ((const float4*)(agg + (size_t)(n0 + 1) * 128))[lid];
    float4 g = ((const float4*)gamma)[lid];
    float4 b = ((const float4*)beta)[lid];
    float inv0 = __fdividef(1.f, sw0 + 1e-8f);
    float inv1 = __fdividef(1.f, sw1 + 1e-8f);
    v0.x *= inv0; v0.y *= inv0; v0.z *= inv0; v0.w *= inv0;
    v1.x *= inv1; v1.y *= inv1; v1.z *= inv1; v1.w *= inv1;
    float s0 = v0.x + v0.y + v0.z + v0.w;
    float q0 = fmaf(v0.x, v0.x, fmaf(v0.y, v0.y, fmaf(v0.z, v0.z, v0.w * v0.w)));
    float s1 = v1.x + v1.y + v1.z + v1.w;
    float q1 = fmaf(v1.x, v1.x, fmaf(v1.y, v1.y, fmaf(v1.z, v1.z, v1.w * v1.w)));
#pragma unroll
    for (int o = 16; o; o >>= 1) {
        s0 += __shfl_xor_sync(0xffffffff, s0, o);
        q0 += __shfl_xor_sync(0xffffffff, q0, o);
        s1 += __shfl_xor_sync(0xffffffff, s1, o);
        q1 += __shfl_xor_sync(0xffffffff, q1, o);
    }
    float mu0 = s0 * (1.f / 128.f);
    float mu1 = s1 * (1.f / 128.f);
    float rs0 = rsqrtf(fmaf(-mu0, mu0, q0 * (1.f / 128.f)) + 1e-5f);
    float rs1 = rsqrtf(fmaf(-mu1, mu1, q1 * (1.f / 128.f)) + 1e-5f);
    ((float4*)(agg + (size_t)n0 * 128))[lid] =
        make_float4((v0.x - mu0) * rs0 * g.x + b.x, (v0.y - mu0) * rs0 * g.y + b.y,
                    (v0.z - mu0) * rs0 * g.z + b.z, (v0.w - mu0) * rs0 * g.w + b.w);
    ((float4*)(agg + (size_t)(n0 + 1) * 128))[lid] =
        make_float4((v1.x - mu1) * rs1 * g.x + b.x, (v1.y - mu1) * rs1 * g.y + b.y,
                    (v1.z - mu1) * rs1 * g.z + b.z, (v1.w - mu1) * rs1 * g.w + b.w);
}

// ---------------- launch ----------------
extern "C" void kernel_launch(void* const* d_in, const int* in_sizes, int n_in,
                              void* d_out, int out_size) {
    const float* msg = (const float*)d_in[0];
    const int* tgt = (const int*)d_in[1];
    const float* nf = (const float*)d_in[2];
    int wi = 3;
    for (int i = 3; i < n_in; i++) {
        if (in_sizes[i] == HDIM * (MDIM + DDIM)) { wi = i; break; }
    }
    const float* W1 = (const float*)d_in[wi];
    const float* b1 = (const float*)d_in[wi + 1];
    const float* W2 = (const float*)d_in[wi + 2];
    const float* gamma = (const float*)d_in[wi + 3];
    const float* beta = (const float*)d_in[wi + 4];
    float* agg = (float*)d_out;

    cudaFuncSetAttribute(pnode_kernel, cudaFuncAttributeMaxDynamicSharedMemorySize, SMEM_BYTES);
    cudaFuncSetAttribute(edge_kernel, cudaFuncAttributeMaxDynamicSharedMemorySize, E_SMEM);

    prep_kernel<<<32, 256>>>(W1);
    pnode_kernel<<<(NNODES + 127) / 128, 128, SMEM_BYTES>>>(nf, b1, agg);
    edge_kernel<<<NEDGES / EM, 128, E_SMEM>>>(msg, tgt, W2, agg);
    finalize_kernel<<<NNODES / 16, 256>>>(agg, gamma, beta);
}